// round 7
// baseline (speedup 1.0000x reference)
#include <cuda_runtime.h>

#define K1v 16
#define BATCH 16
#define CH 32
#define NP 4096
#define EDG (NP*K1v)          // 65536
#define TP 16                 // points per CTA
#define RR 256                // rows per CTA
#define INVC 0.9999950000374997f  // 1/sqrt(1+1e-5)

// Scratch (no cudaMalloc allowed)
__device__ int   g_idx[BATCH*NP*K1v];     // 4 MB
__device__ float g_featT[BATCH*NP*CH];    // 8 MB (B,P,C)
__device__ int   g_brk[BATCH*256];        // per-chunk first-break

typedef unsigned long long u64;

__device__ __forceinline__ u64 fma2(u64 a, u64 b, u64 c) {
    u64 d;
    asm("fma.rn.f32x2 %0, %1, %2, %3;" : "=l"(d) : "l"(a), "l"(b), "l"(c));
    return d;
}
__device__ __forceinline__ u64 pack2(float x, float y) {
    u64 d;
    asm("mov.b64 %0, {%1, %2};" : "=l"(d) : "f"(x), "f"(y));
    return d;
}
__device__ __forceinline__ void unpack2(u64 v, float& x, float& y) {
    asm("mov.b64 {%0, %1}, %2;" : "=f"(x), "=f"(y) : "l"(v));
}

// ---------------------------------------------------------------------------
// Edge preprocessing: prep (defaults + per-chunk break) -> scatter
// ---------------------------------------------------------------------------
__global__ void prep_kernel(const int* __restrict__ ef) {
    const int blk   = blockIdx.x;
    const int b     = blk >> 8;
    const int chunk = blk & 255;
    const int t     = threadIdx.x;         // 256
    const int e     = chunk * 256 + t;

    g_idx[(b << 16) | e] = NP - K1v + (e & 15);   // default idx0

    const int* __restrict__ pf = ef + (size_t)b * 2 * EDG;
    int brk = EDG;
    if (e > 0 && pf[e] == 0 && pf[e - 1] != 0) brk = e;

    __shared__ int s[256];
    s[t] = brk;
    __syncthreads();
    #pragma unroll
    for (int off = 128; off > 0; off >>= 1) {
        if (t < off) s[t] = min(s[t], s[t + off]);
        __syncthreads();
    }
    if (t == 0) g_brk[b * 256 + chunk] = s[0];
}

__global__ void scatter_kernel(const int* __restrict__ ef) {
    const int b  = blockIdx.y;
    const int e0 = blockIdx.x * 256;
    const int t  = threadIdx.x;
    const int e  = e0 + t;
    const int* __restrict__ pf = ef + (size_t)b * 2 * EDG;
    const int* __restrict__ tg = pf + EDG;

    __shared__ int s[272];
    __shared__ int sm2[256];
    sm2[t] = g_brk[b * 256 + t];
    for (int i = t; i < 272; i += 256) {
        int src = e0 - 16 + i;
        s[i] = (src >= 0) ? pf[src] : -1;
    }
    __syncthreads();
    #pragma unroll
    for (int off = 128; off > 0; off >>= 1) {
        if (t < off) sm2[t] = min(sm2[t], sm2[t + off]);
        __syncthreads();
    }
    const int broken = sm2[0];

    int v = s[t + 16];
    int j = 0, m = e, si = t + 16;
    while (m > 0 && j < 16 && s[si - 1] == v) { m--; si--; j++; }
    if (j < 16 && e < broken && (unsigned)v < (unsigned)NP)
        g_idx[(((size_t)b * NP + v) << 4) + j] = tg[e];
}

// ---------------------------------------------------------------------------
// Transpose features (B,C,P) -> (B,P,C)
// ---------------------------------------------------------------------------
__global__ void transpose_kernel(const float* __restrict__ f) {
    __shared__ float tile[32][33];
    int b  = blockIdx.y;
    int p0 = blockIdx.x * 32;
    int tx = threadIdx.x, ty = threadIdx.y;  // (32, 8)
    #pragma unroll
    for (int i = 0; i < 32; i += 8)
        tile[ty + i][tx] = f[((size_t)b * CH + ty + i) * NP + p0 + tx];
    __syncthreads();
    #pragma unroll
    for (int i = 0; i < 32; i += 8)
        g_featT[((size_t)b * NP + p0 + ty + i) * CH + tx] = tile[tx][ty + i];
}

// ---------------------------------------------------------------------------
// GEMM stage (o-sliced warps). Warp owns o-slice [o0, o0+TO) over ALL 256 rows.
// Thread rows: r = g*128 + lane*4 + {0..3}, g = 0,1  (8 rows).
// Weights: pre-duplicated (w,w) u64 in smem -> ulonglong2 broadcast loads.
// X: ulonglong2 loads, 8-lane phases = 128B contiguous (conflict-free).
// MODE 0: dst[o][r] = relu(acc*s + pb0[o][pt]);  MODE 1: bias b[o];
// MODE 2: red[o][pt] = sum over rows of relu(acc*s + b[o])  (shfl over lane&3).
// ---------------------------------------------------------------------------
template<int TO, int MODE>
__device__ __forceinline__ void gemm_stage(
    const float* __restrict__ src,   // [32][256]
    float*       __restrict__ dst,
    const u64*   __restrict__ Wd,    // [32][OTOT] dup'd weights
    int OTOT, int o0,
    const float* __restrict__ scal, const float* __restrict__ bias,
    const float* __restrict__ pb0s,
    int lane)
{
    u64 acc[TO][4];
    #pragma unroll
    for (int o = 0; o < TO; o++)
        #pragma unroll
        for (int j = 0; j < 4; j++) acc[o][j] = 0ull;

    const float* xb = src + lane * 4;

    #pragma unroll 8
    for (int k = 0; k < 32; k++) {
        u64 xp[4];
        {
            ulonglong2 x0 = *(const ulonglong2*)(xb + k * RR);
            ulonglong2 x1 = *(const ulonglong2*)(xb + k * RR + 128);
            xp[0] = x0.x; xp[1] = x0.y; xp[2] = x1.x; xp[3] = x1.y;
        }
        const u64* wrow = Wd + k * OTOT + o0;
        #pragma unroll
        for (int t = 0; t < TO / 2; t++) {
            ulonglong2 wv = *(const ulonglong2*)(wrow + 2 * t);
            #pragma unroll
            for (int j = 0; j < 4; j++)
                acc[2*t][j]   = fma2(wv.x, xp[j], acc[2*t][j]);
            #pragma unroll
            for (int j = 0; j < 4; j++)
                acc[2*t+1][j] = fma2(wv.y, xp[j], acc[2*t+1][j]);
        }
    }

    const int ptq = lane >> 2;   // + g*8

    #pragma unroll
    for (int o = 0; o < TO; o++) {
        int og = o0 + o;
        float s = scal[og];
        if (MODE == 2) {
            float bv = bias[og];
            #pragma unroll
            for (int g = 0; g < 2; g++) {
                float h0, h1, h2, h3;
                unpack2(acc[o][2*g],   h0, h1);
                unpack2(acc[o][2*g+1], h2, h3);
                float pa = fmaxf(fmaf(h0, s, bv), 0.f) + fmaxf(fmaf(h1, s, bv), 0.f)
                         + fmaxf(fmaf(h2, s, bv), 0.f) + fmaxf(fmaf(h3, s, bv), 0.f);
                pa += __shfl_xor_sync(0xffffffffu, pa, 1);
                pa += __shfl_xor_sync(0xffffffffu, pa, 2);
                if ((lane & 3) == 0)
                    dst[og * TP + g * 8 + ptq] = pa;
            }
        } else {
            #pragma unroll
            for (int g = 0; g < 2; g++) {
                float bv = (MODE == 0) ? pb0s[og * TP + g * 8 + ptq] : bias[og];
                float h0, h1, h2, h3;
                unpack2(acc[o][2*g],   h0, h1);
                unpack2(acc[o][2*g+1], h2, h3);
                h0 = fmaxf(fmaf(h0, s, bv), 0.f);
                h1 = fmaxf(fmaf(h1, s, bv), 0.f);
                h2 = fmaxf(fmaf(h2, s, bv), 0.f);
                h3 = fmaxf(fmaf(h3, s, bv), 0.f);
                *(float4*)(dst + og * RR + g * 128 + lane * 4)
                    = make_float4(h0, h1, h2, h3);
            }
        }
    }
}

// ---------------------------------------------------------------------------
// Main kernel, 128 threads, TP=16 points (256 rows), 2 CTAs/SM.
// Smem layout (float offsets), 29056 floats = 113.5 KB:
//   0     sW0hd [32c][32o x2dup]   (u64 view: [c][32])
//   2048  sW1d  [32c][32o x2dup]
//   4096  sW2d  [32c][64o x2dup]
//   8192  sWtc  [32c][64o]
//   10240 ss0,sb0,ss1,sb1 (32 ea)
//   10368 ss2,sb2,ssc,sbc (64 ea)
//   10624 CF[32c][16]   11136 pb0s[32o][16]   11648 red[64o][16]
//   12672 XA[32][256]   20864 XB[32][256]
// ---------------------------------------------------------------------------
#define SMEM_FLOATS 29056

__global__ void __launch_bounds__(128, 2) main_kernel(
    const float* __restrict__ W0, const float* __restrict__ g0, const float* __restrict__ bb0,
    const float* __restrict__ W1, const float* __restrict__ g1, const float* __restrict__ bb1,
    const float* __restrict__ W2, const float* __restrict__ g2, const float* __restrict__ bb2,
    const float* __restrict__ SW, const float* __restrict__ sg, const float* __restrict__ sb,
    float* __restrict__ out)
{
    extern __shared__ float sm[];
    u64*   sW0hd = (u64*)(sm);          // [32][32] u64
    u64*   sW1d  = (u64*)(sm + 2048);   // [32][32] u64
    u64*   sW2d  = (u64*)(sm + 4096);   // [32][64] u64
    float* sWtc  = sm + 8192;
    float* ss0   = sm + 10240;
    float* sb0   = sm + 10272;
    float* ss1   = sm + 10304;
    float* sb1   = sm + 10336;
    float* ss2   = sm + 10368;
    float* sb2   = sm + 10432;
    float* ssc   = sm + 10496;
    float* sbc   = sm + 10560;
    float* CF    = sm + 10624;
    float* pb0s  = sm + 11136;
    float* red   = sm + 11648;
    float* XA    = sm + 12672;
    float* XB    = sm + 20864;

    const int tid  = threadIdx.x;
    const int base = blockIdx.x * TP;
    const int b    = base >> 12;
    const int p0   = base & (NP - 1);

    // ---- stage duplicated weights + scales ----
    for (int i = tid; i < 2048; i += 128) {        // W0: (32o, 64c); high half only
        int o = i >> 6, c = i & 63;
        if (c >= 32) {
            float w = W0[i];
            sW0hd[(c - 32) * 32 + o] = pack2(w, w);
        }
    }
    for (int i = tid; i < 1024; i += 128) {        // W1: (32o, 32c)
        int o = i >> 5, c = i & 31;
        float w = W1[i];
        sW1d[c * 32 + o] = pack2(w, w);
    }
    for (int i = tid; i < 2048; i += 128) {        // W2: (64o, 32c)
        int o = i >> 5, c = i & 31;
        float w = W2[i];
        sW2d[c * 64 + o] = pack2(w, w);
    }
    for (int i = tid; i < 2048; i += 128) {        // SW (shortcut)
        int o = i >> 5, c = i & 31;
        sWtc[c * 64 + o] = SW[i];
    }
    if (tid < 32) { ss0[tid] = g0[tid] * INVC; sb0[tid] = bb0[tid];
                    ss1[tid] = g1[tid] * INVC; sb1[tid] = bb1[tid]; }
    else if (tid < 96) { int o = tid - 32;
                    ss2[o] = g2[o] * INVC; sb2[o] = bb2[o];
                    ssc[o] = sg[o] * INVC; sbc[o] = sb[o]; }

    const float* __restrict__ fT = g_featT + (size_t)b * NP * CH;

    // ---- stage CF[c][pt] ----
    {
        int pt = tid >> 3;
        int c0 = (tid & 7) * 4;
        float4 v = *(const float4*)(fT + (size_t)(p0 + pt) * CH + c0);
        CF[(c0+0) * TP + pt] = v.x;
        CF[(c0+1) * TP + pt] = v.y;
        CF[(c0+2) * TP + pt] = v.z;
        CF[(c0+3) * TP + pt] = v.w;
    }

    // ---- stage XH: thread handles rows 2*tid, 2*tid+1 (same pt) ----
    {
        int r0s = tid * 2;
        int pt  = r0s >> 4;
        int k0  = r0s & 15;
        const int* ipp = g_idx + (((size_t)b * NP + p0 + pt) << 4);
        int q0 = ipp[k0];
        int q1 = ipp[k0 + 1];
        const float4* qa = (const float4*)(fT + (size_t)q0 * CH);
        const float4* qb = (const float4*)(fT + (size_t)q1 * CH);
        const float4* pp = (const float4*)(fT + (size_t)(p0 + pt) * CH);
        #pragma unroll
        for (int i = 0; i < 8; i++) {
            float4 a0 = qa[i], a1 = qb[i], cv = pp[i];
            *(float2*)(XA + (4*i+0) * RR + r0s) = make_float2(a0.x - cv.x, a1.x - cv.x);
            *(float2*)(XA + (4*i+1) * RR + r0s) = make_float2(a0.y - cv.y, a1.y - cv.y);
            *(float2*)(XA + (4*i+2) * RR + r0s) = make_float2(a0.z - cv.z, a1.z - cv.z);
            *(float2*)(XA + (4*i+3) * RR + r0s) = make_float2(a0.w - cv.w, a1.w - cv.w);
        }
    }
    __syncthreads();

    // ---- pb0[o][pt]: W0 low half read from global (L2-resident, 4KB) ----
    {
        int pt  = tid & 15;
        int o0p = (tid >> 4) * 4;      // 8 groups x 4 o = 32 o
        float a[4] = {0.f, 0.f, 0.f, 0.f};
        #pragma unroll
        for (int j = 0; j < 4; j++) {
            const float* wr = W0 + (o0p + j) * 64;   // low half = first 32
            float acc = 0.f;
            #pragma unroll
            for (int c4 = 0; c4 < 8; c4++) {
                float4 w = *(const float4*)(wr + c4 * 4);
                acc = fmaf(w.x, CF[(c4*4+0) * TP + pt], acc);
                acc = fmaf(w.y, CF[(c4*4+1) * TP + pt], acc);
                acc = fmaf(w.z, CF[(c4*4+2) * TP + pt], acc);
                acc = fmaf(w.w, CF[(c4*4+3) * TP + pt], acc);
            }
            a[j] = acc;
        }
        #pragma unroll
        for (int j = 0; j < 4; j++) {
            int o = o0p + j;
            pb0s[o * TP + pt] = fmaf(a[j], ss0[o], sb0[o]);
        }
    }
    __syncthreads();

    const int w_   = tid >> 5;
    const int lane = tid & 31;

    gemm_stage<8, 0>(XA, XB, sW0hd, 32, w_ * 8,  ss0, sb0, pb0s, lane);
    __syncthreads();
    gemm_stage<8, 1>(XB, XA, sW1d,  32, w_ * 8,  ss1, sb1, pb0s, lane);
    __syncthreads();
    gemm_stage<16, 2>(XA, red, sW2d, 64, w_ * 16, ss2, sb2, pb0s, lane);
    __syncthreads();

    // ---- shortcut + mean + final relu (coalesced: pt fastest) ----
    {
        int pt  = tid & 15;
        int o0s = (tid >> 4) * 8;      // 8 groups x 8 o = 64 o
        float a[8];
        #pragma unroll
        for (int j = 0; j < 8; j++) a[j] = 0.f;
        #pragma unroll
        for (int c = 0; c < 32; c++) {
            float cf = CF[c * TP + pt];
            float4 w0 = *(const float4*)(sWtc + c * 64 + o0s);
            float4 w1 = *(const float4*)(sWtc + c * 64 + o0s + 4);
            a[0] = fmaf(w0.x, cf, a[0]); a[1] = fmaf(w0.y, cf, a[1]);
            a[2] = fmaf(w0.z, cf, a[2]); a[3] = fmaf(w0.w, cf, a[3]);
            a[4] = fmaf(w1.x, cf, a[4]); a[5] = fmaf(w1.y, cf, a[5]);
            a[6] = fmaf(w1.z, cf, a[6]); a[7] = fmaf(w1.w, cf, a[7]);
        }
        #pragma unroll
        for (int j = 0; j < 8; j++) {
            int o = o0s + j;
            float v = fmaf(a[j], ssc[o], sbc[o]) + red[o * TP + pt] * (1.0f / 16.0f);
            out[((size_t)b * 64 + o) * NP + p0 + pt] = fmaxf(v, 0.f);
        }
    }
}

// ---------------------------------------------------------------------------
extern "C" void kernel_launch(void* const* d_in, const int* in_sizes, int n_in,
                              void* d_out, int out_size)
{
    (void)in_sizes; (void)n_in; (void)out_size;
    const float* features = (const float*)d_in[1];
    const int*   ef       = (const int*)d_in[2];

    static bool attr_set = false;
    if (!attr_set) {
        cudaFuncSetAttribute(main_kernel,
                             cudaFuncAttributeMaxDynamicSharedMemorySize,
                             SMEM_FLOATS * (int)sizeof(float));
        attr_set = true;
    }

    prep_kernel<<<BATCH * 256, 256>>>(ef);
    {
        dim3 tg(EDG / 256, BATCH);
        scatter_kernel<<<tg, 256>>>(ef);
    }
    {
        dim3 tb(32, 8), tg(NP / 32, BATCH);
        transpose_kernel<<<tg, tb>>>(features);
    }
    main_kernel<<<(BATCH * NP) / TP, 128, SMEM_FLOATS * sizeof(float)>>>(
        (const float*)d_in[3],  (const float*)d_in[4],  (const float*)d_in[5],
        (const float*)d_in[6],  (const float*)d_in[7],  (const float*)d_in[8],
        (const float*)d_in[9],  (const float*)d_in[10], (const float*)d_in[11],
        (const float*)d_in[12], (const float*)d_in[13], (const float*)d_in[14],
        (float*)d_out);
}

// round 8
// speedup vs baseline: 1.2954x; 1.2954x over previous
#include <cuda_runtime.h>

#define K1v 16
#define BATCH 16
#define CH 32
#define NP 4096
#define EDG (NP*K1v)          // 65536
#define TP 16                 // points per CTA
#define RR 256                // rows per CTA
#define INVC 0.9999950000374997f  // 1/sqrt(1+1e-5)

// Scratch (no cudaMalloc allowed)
__device__ int   g_idx[BATCH*NP*K1v];     // 4 MB
__device__ float g_featT[BATCH*NP*CH];    // 8 MB (B,P,C)
__device__ int   g_brk[BATCH*256];        // per-chunk first-break

typedef unsigned long long u64;

__device__ __forceinline__ u64 fma2(u64 a, u64 b, u64 c) {
    u64 d;
    asm("fma.rn.f32x2 %0, %1, %2, %3;" : "=l"(d) : "l"(a), "l"(b), "l"(c));
    return d;
}
__device__ __forceinline__ u64 pack2(float x, float y) {
    u64 d;
    asm("mov.b64 %0, {%1, %2};" : "=l"(d) : "f"(x), "f"(y));
    return d;
}
__device__ __forceinline__ void unpack2(u64 v, float& x, float& y) {
    asm("mov.b64 {%0, %1}, %2;" : "=f"(x), "=f"(y) : "l"(v));
}

// ---------------------------------------------------------------------------
// Edge preprocessing: prep (defaults + per-chunk break) -> scatter
// ---------------------------------------------------------------------------
__global__ void prep_kernel(const int* __restrict__ ef) {
    const int blk   = blockIdx.x;
    const int b     = blk >> 8;
    const int chunk = blk & 255;
    const int t     = threadIdx.x;         // 256
    const int e     = chunk * 256 + t;

    g_idx[(b << 16) | e] = NP - K1v + (e & 15);   // default idx0

    const int* __restrict__ pf = ef + (size_t)b * 2 * EDG;
    int brk = EDG;
    if (e > 0 && pf[e] == 0 && pf[e - 1] != 0) brk = e;

    __shared__ int s[256];
    s[t] = brk;
    __syncthreads();
    #pragma unroll
    for (int off = 128; off > 0; off >>= 1) {
        if (t < off) s[t] = min(s[t], s[t + off]);
        __syncthreads();
    }
    if (t == 0) g_brk[b * 256 + chunk] = s[0];
}

__global__ void scatter_kernel(const int* __restrict__ ef) {
    const int b  = blockIdx.y;
    const int e0 = blockIdx.x * 256;
    const int t  = threadIdx.x;
    const int e  = e0 + t;
    const int* __restrict__ pf = ef + (size_t)b * 2 * EDG;
    const int* __restrict__ tg = pf + EDG;

    __shared__ int s[272];
    __shared__ int sm2[256];
    sm2[t] = g_brk[b * 256 + t];
    for (int i = t; i < 272; i += 256) {
        int src = e0 - 16 + i;
        s[i] = (src >= 0) ? pf[src] : -1;
    }
    __syncthreads();
    #pragma unroll
    for (int off = 128; off > 0; off >>= 1) {
        if (t < off) sm2[t] = min(sm2[t], sm2[t + off]);
        __syncthreads();
    }
    const int broken = sm2[0];

    int v = s[t + 16];
    int j = 0, m = e, si = t + 16;
    while (m > 0 && j < 16 && s[si - 1] == v) { m--; si--; j++; }
    if (j < 16 && e < broken && (unsigned)v < (unsigned)NP)
        g_idx[(((size_t)b * NP + v) << 4) + j] = tg[e];
}

// ---------------------------------------------------------------------------
// Transpose features (B,C,P) -> (B,P,C)
// ---------------------------------------------------------------------------
__global__ void transpose_kernel(const float* __restrict__ f) {
    __shared__ float tile[32][33];
    int b  = blockIdx.y;
    int p0 = blockIdx.x * 32;
    int tx = threadIdx.x, ty = threadIdx.y;  // (32, 8)
    #pragma unroll
    for (int i = 0; i < 32; i += 8)
        tile[ty + i][tx] = f[((size_t)b * CH + ty + i) * NP + p0 + tx];
    __syncthreads();
    #pragma unroll
    for (int i = 0; i < 32; i += 8)
        g_featT[((size_t)b * NP + p0 + ty + i) * CH + tx] = tile[tx][ty + i];
}

// ---------------------------------------------------------------------------
// GEMM stage (o-sliced warps, SCALAR weight broadcasts).
// Warp owns o-slice [o0, o0+TO) over ALL 256 rows.
// Weights stored [o][k] (stride 32): per-k loads are non-contiguous scalars ->
// each is a single-wavefront LDS.32 broadcast; dup to u64 in regs (alu pipe).
// X: 2x ulonglong2, 8-lane phases = 128B contiguous (all phases useful).
// MODE 0: dst[o][r] = relu(acc*s + pb0[o][pt]);  MODE 1: bias b[o];
// MODE 2: red[o][pt] = sum over rows of relu(acc*s + b[o])  (shfl over lane&3).
// ---------------------------------------------------------------------------
template<int TO, int MODE>
__device__ __forceinline__ void gemm_stage(
    const float* __restrict__ src,   // [32][256]
    float*       __restrict__ dst,
    const float* __restrict__ Wok,   // [Ototal][32]  ([o][k])
    int o0,
    const float* __restrict__ scal, const float* __restrict__ bias,
    const float* __restrict__ pb0s,
    int lane)
{
    u64 acc[TO][4];
    #pragma unroll
    for (int o = 0; o < TO; o++)
        #pragma unroll
        for (int j = 0; j < 4; j++) acc[o][j] = 0ull;

    const float* xb = src + lane * 4;
    const float* wb = Wok + o0 * 32;

    #pragma unroll 8
    for (int k = 0; k < 32; k++) {
        u64 xp[4];
        {
            ulonglong2 x0 = *(const ulonglong2*)(xb + k * RR);
            ulonglong2 x1 = *(const ulonglong2*)(xb + k * RR + 128);
            xp[0] = x0.x; xp[1] = x0.y; xp[2] = x1.x; xp[3] = x1.y;
        }
        #pragma unroll
        for (int o = 0; o < TO; o++) {
            float wv = wb[o * 32 + k];        // scalar LDS.32 broadcast (1 wf)
            u64 wd = pack2(wv, wv);
            acc[o][0] = fma2(wd, xp[0], acc[o][0]);
            acc[o][1] = fma2(wd, xp[1], acc[o][1]);
            acc[o][2] = fma2(wd, xp[2], acc[o][2]);
            acc[o][3] = fma2(wd, xp[3], acc[o][3]);
        }
    }

    const int ptq = lane >> 2;   // + g*8

    #pragma unroll
    for (int o = 0; o < TO; o++) {
        int og = o0 + o;
        float s = scal[og];
        if (MODE == 2) {
            float bv = bias[og];
            #pragma unroll
            for (int g = 0; g < 2; g++) {
                float h0, h1, h2, h3;
                unpack2(acc[o][2*g],   h0, h1);
                unpack2(acc[o][2*g+1], h2, h3);
                float pa = fmaxf(fmaf(h0, s, bv), 0.f) + fmaxf(fmaf(h1, s, bv), 0.f)
                         + fmaxf(fmaf(h2, s, bv), 0.f) + fmaxf(fmaf(h3, s, bv), 0.f);
                pa += __shfl_xor_sync(0xffffffffu, pa, 1);
                pa += __shfl_xor_sync(0xffffffffu, pa, 2);
                if ((lane & 3) == 0)
                    dst[og * TP + g * 8 + ptq] = pa;
            }
        } else {
            #pragma unroll
            for (int g = 0; g < 2; g++) {
                float bv = (MODE == 0) ? pb0s[og * TP + g * 8 + ptq] : bias[og];
                float h0, h1, h2, h3;
                unpack2(acc[o][2*g],   h0, h1);
                unpack2(acc[o][2*g+1], h2, h3);
                h0 = fmaxf(fmaf(h0, s, bv), 0.f);
                h1 = fmaxf(fmaf(h1, s, bv), 0.f);
                h2 = fmaxf(fmaf(h2, s, bv), 0.f);
                h3 = fmaxf(fmaf(h3, s, bv), 0.f);
                *(float4*)(dst + og * RR + g * 128 + lane * 4)
                    = make_float4(h0, h1, h2, h3);
            }
        }
    }
}

// ---------------------------------------------------------------------------
// Main kernel, 128 threads, TP=16 points (256 rows), 2 CTAs/SM.
// Smem layout (float offsets), 24960 floats = 97.5 KB:
//   0     sW0h [32o][32k]      1024  sW1 [32o][32k]     2048  sW2 [64o][32k]
//   4096  sWtc [32c][64o]
//   6144  ss0,sb0,ss1,sb1 (32 ea)     6272  ss2,sb2,ssc,sbc (64 ea)
//   6528  CF[32c][16]   7040 pb0s[32o][16]   7552 red[64o][16]
//   8576  XA[32][256]   16768 XB[32][256]
// ---------------------------------------------------------------------------
#define SMEM_FLOATS 24960

__global__ void __launch_bounds__(128, 2) main_kernel(
    const float* __restrict__ W0, const float* __restrict__ g0, const float* __restrict__ bb0,
    const float* __restrict__ W1, const float* __restrict__ g1, const float* __restrict__ bb1,
    const float* __restrict__ W2, const float* __restrict__ g2, const float* __restrict__ bb2,
    const float* __restrict__ SW, const float* __restrict__ sg, const float* __restrict__ sb,
    float* __restrict__ out)
{
    extern __shared__ float sm[];
    float* sW0h  = sm;           // [32o][32k]
    float* sW1s  = sm + 1024;    // [32o][32k]
    float* sW2s  = sm + 2048;    // [64o][32k]
    float* sWtc  = sm + 4096;    // [32c][64o]
    float* ss0   = sm + 6144;
    float* sb0   = sm + 6176;
    float* ss1   = sm + 6208;
    float* sb1   = sm + 6240;
    float* ss2   = sm + 6272;
    float* sb2   = sm + 6336;
    float* ssc   = sm + 6400;
    float* sbc   = sm + 6464;
    float* CF    = sm + 6528;
    float* pb0s  = sm + 7040;
    float* red   = sm + 7552;
    float* XA    = sm + 8576;
    float* XB    = sm + 16768;

    const int tid  = threadIdx.x;
    const int base = blockIdx.x * TP;
    const int b    = base >> 12;
    const int p0   = base & (NP - 1);

    // ---- stage weights ([o][k] layout) + scales ----
    for (int i = tid; i < 1024; i += 128) {        // W0 high half: o=i>>5, k=i&31
        int o = i >> 5, k = i & 31;
        sW0h[i] = W0[o * 64 + 32 + k];
    }
    for (int i = tid; i < 1024; i += 128)          // W1 already (o,k) row-major
        sW1s[i] = W1[i];
    for (int i = tid; i < 2048; i += 128)          // W2 (o,k) row-major
        sW2s[i] = W2[i];
    for (int i = tid; i < 2048; i += 128) {        // SW (shortcut) -> [c][o]
        int o = i >> 5, c = i & 31;
        sWtc[c * 64 + o] = SW[i];
    }
    if (tid < 32) { ss0[tid] = g0[tid] * INVC; sb0[tid] = bb0[tid];
                    ss1[tid] = g1[tid] * INVC; sb1[tid] = bb1[tid]; }
    else if (tid < 96) { int o = tid - 32;
                    ss2[o] = g2[o] * INVC; sb2[o] = bb2[o];
                    ssc[o] = sg[o] * INVC; sbc[o] = sb[o]; }

    const float* __restrict__ fT = g_featT + (size_t)b * NP * CH;

    // ---- stage CF[c][pt] ----
    {
        int pt = tid >> 3;
        int c0 = (tid & 7) * 4;
        float4 v = *(const float4*)(fT + (size_t)(p0 + pt) * CH + c0);
        CF[(c0+0) * TP + pt] = v.x;
        CF[(c0+1) * TP + pt] = v.y;
        CF[(c0+2) * TP + pt] = v.z;
        CF[(c0+3) * TP + pt] = v.w;
    }

    // ---- stage XH: thread handles rows 2*tid, 2*tid+1 (same pt) ----
    {
        int r0s = tid * 2;
        int pt  = r0s >> 4;
        int k0  = r0s & 15;
        const int* ipp = g_idx + (((size_t)b * NP + p0 + pt) << 4);
        int q0 = ipp[k0];
        int q1 = ipp[k0 + 1];
        const float4* qa = (const float4*)(fT + (size_t)q0 * CH);
        const float4* qb = (const float4*)(fT + (size_t)q1 * CH);
        const float4* pp = (const float4*)(fT + (size_t)(p0 + pt) * CH);
        #pragma unroll
        for (int i = 0; i < 8; i++) {
            float4 a0 = qa[i], a1 = qb[i], cv = pp[i];
            *(float2*)(XA + (4*i+0) * RR + r0s) = make_float2(a0.x - cv.x, a1.x - cv.x);
            *(float2*)(XA + (4*i+1) * RR + r0s) = make_float2(a0.y - cv.y, a1.y - cv.y);
            *(float2*)(XA + (4*i+2) * RR + r0s) = make_float2(a0.z - cv.z, a1.z - cv.z);
            *(float2*)(XA + (4*i+3) * RR + r0s) = make_float2(a0.w - cv.w, a1.w - cv.w);
        }
    }
    __syncthreads();

    // ---- pb0[o][pt]: W0 low half read from global (L2-resident, 4KB) ----
    {
        int pt  = tid & 15;
        int o0p = (tid >> 4) * 4;      // 8 groups x 4 o = 32 o
        float a[4] = {0.f, 0.f, 0.f, 0.f};
        #pragma unroll
        for (int j = 0; j < 4; j++) {
            const float* wr = W0 + (o0p + j) * 64;   // low half = first 32
            float acc = 0.f;
            #pragma unroll
            for (int c4 = 0; c4 < 8; c4++) {
                float4 w = *(const float4*)(wr + c4 * 4);
                acc = fmaf(w.x, CF[(c4*4+0) * TP + pt], acc);
                acc = fmaf(w.y, CF[(c4*4+1) * TP + pt], acc);
                acc = fmaf(w.z, CF[(c4*4+2) * TP + pt], acc);
                acc = fmaf(w.w, CF[(c4*4+3) * TP + pt], acc);
            }
            a[j] = acc;
        }
        #pragma unroll
        for (int j = 0; j < 4; j++) {
            int o = o0p + j;
            pb0s[o * TP + pt] = fmaf(a[j], ss0[o], sb0[o]);
        }
    }
    __syncthreads();

    const int w_   = tid >> 5;
    const int lane = tid & 31;

    gemm_stage<8, 0>(XA, XB, sW0h, w_ * 8,  ss0, sb0, pb0s, lane);
    __syncthreads();
    gemm_stage<8, 1>(XB, XA, sW1s, w_ * 8,  ss1, sb1, pb0s, lane);
    __syncthreads();
    gemm_stage<16, 2>(XA, red, sW2s, w_ * 16, ss2, sb2, pb0s, lane);
    __syncthreads();

    // ---- shortcut + mean + final relu (coalesced: pt fastest) ----
    {
        int pt  = tid & 15;
        int o0s = (tid >> 4) * 8;      // 8 groups x 8 o = 64 o
        float a[8];
        #pragma unroll
        for (int j = 0; j < 8; j++) a[j] = 0.f;
        #pragma unroll
        for (int c = 0; c < 32; c++) {
            float cf = CF[c * TP + pt];
            float4 w0 = *(const float4*)(sWtc + c * 64 + o0s);
            float4 w1 = *(const float4*)(sWtc + c * 64 + o0s + 4);
            a[0] = fmaf(w0.x, cf, a[0]); a[1] = fmaf(w0.y, cf, a[1]);
            a[2] = fmaf(w0.z, cf, a[2]); a[3] = fmaf(w0.w, cf, a[3]);
            a[4] = fmaf(w1.x, cf, a[4]); a[5] = fmaf(w1.y, cf, a[5]);
            a[6] = fmaf(w1.z, cf, a[6]); a[7] = fmaf(w1.w, cf, a[7]);
        }
        #pragma unroll
        for (int j = 0; j < 8; j++) {
            int o = o0s + j;
            float v = fmaf(a[j], ssc[o], sbc[o]) + red[o * TP + pt] * (1.0f / 16.0f);
            out[((size_t)b * 64 + o) * NP + p0 + pt] = fmaxf(v, 0.f);
        }
    }
}

// ---------------------------------------------------------------------------
extern "C" void kernel_launch(void* const* d_in, const int* in_sizes, int n_in,
                              void* d_out, int out_size)
{
    (void)in_sizes; (void)n_in; (void)out_size;
    const float* features = (const float*)d_in[1];
    const int*   ef       = (const int*)d_in[2];

    static bool attr_set = false;
    if (!attr_set) {
        cudaFuncSetAttribute(main_kernel,
                             cudaFuncAttributeMaxDynamicSharedMemorySize,
                             SMEM_FLOATS * (int)sizeof(float));
        attr_set = true;
    }

    prep_kernel<<<BATCH * 256, 256>>>(ef);
    {
        dim3 tg(EDG / 256, BATCH);
        scatter_kernel<<<tg, 256>>>(ef);
    }
    {
        dim3 tb(32, 8), tg(NP / 32, BATCH);
        transpose_kernel<<<tg, tb>>>(features);
    }
    main_kernel<<<(BATCH * NP) / TP, 128, SMEM_FLOATS * sizeof(float)>>>(
        (const float*)d_in[3],  (const float*)d_in[4],  (const float*)d_in[5],
        (const float*)d_in[6],  (const float*)d_in[7],  (const float*)d_in[8],
        (const float*)d_in[9],  (const float*)d_in[10], (const float*)d_in[11],
        (const float*)d_in[12], (const float*)d_in[13], (const float*)d_in[14],
        (float*)d_out);
}

// round 9
// speedup vs baseline: 1.3227x; 1.0211x over previous
#include <cuda_runtime.h>

#define K1v 16
#define BATCH 16
#define CH 32
#define NP 4096
#define EDG (NP*K1v)          // 65536
#define TP 16                 // points per CTA
#define RR 256                // rows per CTA
#define INVC 0.9999950000374997f  // 1/sqrt(1+1e-5)

// Scratch (no cudaMalloc allowed)
__device__ int   g_idx[BATCH*NP*K1v];     // 4 MB
__device__ float g_featT[BATCH*NP*CH];    // 8 MB (B,P,C)
__device__ int   g_brk[BATCH*256];        // per-chunk first-break

typedef unsigned long long u64;

__device__ __forceinline__ u64 fma2(u64 a, u64 b, u64 c) {
    u64 d;
    asm("fma.rn.f32x2 %0, %1, %2, %3;" : "=l"(d) : "l"(a), "l"(b), "l"(c));
    return d;
}
__device__ __forceinline__ u64 pack2(float x, float y) {
    u64 d;
    asm("mov.b64 %0, {%1, %2};" : "=l"(d) : "f"(x), "f"(y));
    return d;
}
__device__ __forceinline__ void unpack2(u64 v, float& x, float& y) {
    asm("mov.b64 {%0, %1}, %2;" : "=f"(x), "=f"(y) : "l"(v));
}

// ---------------------------------------------------------------------------
// Edge preprocessing: prep (defaults + per-chunk break) -> scatter
// ---------------------------------------------------------------------------
__global__ void prep_kernel(const int* __restrict__ ef) {
    const int blk   = blockIdx.x;
    const int b     = blk >> 8;
    const int chunk = blk & 255;
    const int t     = threadIdx.x;         // 256
    const int e     = chunk * 256 + t;

    g_idx[(b << 16) | e] = NP - K1v + (e & 15);   // default idx0

    const int* __restrict__ pf = ef + (size_t)b * 2 * EDG;
    int brk = EDG;
    if (e > 0 && pf[e] == 0 && pf[e - 1] != 0) brk = e;

    __shared__ int s[256];
    s[t] = brk;
    __syncthreads();
    #pragma unroll
    for (int off = 128; off > 0; off >>= 1) {
        if (t < off) s[t] = min(s[t], s[t + off]);
        __syncthreads();
    }
    if (t == 0) g_brk[b * 256 + chunk] = s[0];
}

__global__ void scatter_kernel(const int* __restrict__ ef) {
    const int b  = blockIdx.y;
    const int e0 = blockIdx.x * 256;
    const int t  = threadIdx.x;
    const int e  = e0 + t;
    const int* __restrict__ pf = ef + (size_t)b * 2 * EDG;
    const int* __restrict__ tg = pf + EDG;

    __shared__ int s[272];
    __shared__ int sm2[256];
    sm2[t] = g_brk[b * 256 + t];
    for (int i = t; i < 272; i += 256) {
        int src = e0 - 16 + i;
        s[i] = (src >= 0) ? pf[src] : -1;
    }
    __syncthreads();
    #pragma unroll
    for (int off = 128; off > 0; off >>= 1) {
        if (t < off) sm2[t] = min(sm2[t], sm2[t + off]);
        __syncthreads();
    }
    const int broken = sm2[0];

    int v = s[t + 16];
    int j = 0, m = e, si = t + 16;
    while (m > 0 && j < 16 && s[si - 1] == v) { m--; si--; j++; }
    if (j < 16 && e < broken && (unsigned)v < (unsigned)NP)
        g_idx[(((size_t)b * NP + v) << 4) + j] = tg[e];
}

// ---------------------------------------------------------------------------
// Transpose features (B,C,P) -> (B,P,C)
// ---------------------------------------------------------------------------
__global__ void transpose_kernel(const float* __restrict__ f) {
    __shared__ float tile[32][33];
    int b  = blockIdx.y;
    int p0 = blockIdx.x * 32;
    int tx = threadIdx.x, ty = threadIdx.y;  // (32, 8)
    #pragma unroll
    for (int i = 0; i < 32; i += 8)
        tile[ty + i][tx] = f[((size_t)b * CH + ty + i) * NP + p0 + tx];
    __syncthreads();
    #pragma unroll
    for (int i = 0; i < 32; i += 8)
        g_featT[((size_t)b * NP + p0 + ty + i) * CH + tx] = tile[tx][ty + i];
}

// ---------------------------------------------------------------------------
// GEMM stage (o-sliced warps, DUPLICATED u64 weight broadcasts).
// Warp owns o-slice [o0, o0+8) over ALL 256 rows.
// Weights stored dup'd u64 [o][k] (o-stride 256B): per-(o,k) load is a
// single LDS.64 uniform broadcast feeding fma2 directly (no pack MOVs).
// X: 2x ulonglong2, 8-lane phases = 128B contiguous.
// MODE 0: dst[o][r] = relu(acc*s + pb0[o][pt]);  MODE 1: bias b[o];
// MODE 2: red[o][pt] = sum over rows of relu(acc*s + b[o])  (shfl over lane&3).
// ---------------------------------------------------------------------------
template<int MODE>
__device__ __forceinline__ void gemm_stage(
    const float* __restrict__ src,   // [32][256]
    float*       __restrict__ dst,
    const u64*   __restrict__ Wd,    // [Ototal][32] dup'd ([o][k])
    int o0,
    const float* __restrict__ scal, const float* __restrict__ bias,
    const float* __restrict__ pb0s,
    int lane)
{
    u64 acc[8][4];
    #pragma unroll
    for (int o = 0; o < 8; o++)
        #pragma unroll
        for (int j = 0; j < 4; j++) acc[o][j] = 0ull;

    const float* xb = src + lane * 4;
    const u64*   wb = Wd + o0 * 32;

    #pragma unroll 8
    for (int k = 0; k < 32; k++) {
        u64 xp[4];
        {
            ulonglong2 x0 = *(const ulonglong2*)(xb + k * RR);
            ulonglong2 x1 = *(const ulonglong2*)(xb + k * RR + 128);
            xp[0] = x0.x; xp[1] = x0.y; xp[2] = x1.x; xp[3] = x1.y;
        }
        #pragma unroll
        for (int o = 0; o < 8; o++) {
            u64 wd = wb[o * 32 + k];          // LDS.64 uniform broadcast
            acc[o][0] = fma2(wd, xp[0], acc[o][0]);
            acc[o][1] = fma2(wd, xp[1], acc[o][1]);
            acc[o][2] = fma2(wd, xp[2], acc[o][2]);
            acc[o][3] = fma2(wd, xp[3], acc[o][3]);
        }
    }

    const int ptq = lane >> 2;   // + g*8

    #pragma unroll
    for (int o = 0; o < 8; o++) {
        int og = o0 + o;
        float s = scal[og];
        if (MODE == 2) {
            float bv = bias[og];
            #pragma unroll
            for (int g = 0; g < 2; g++) {
                float h0, h1, h2, h3;
                unpack2(acc[o][2*g],   h0, h1);
                unpack2(acc[o][2*g+1], h2, h3);
                float pa = fmaxf(fmaf(h0, s, bv), 0.f) + fmaxf(fmaf(h1, s, bv), 0.f)
                         + fmaxf(fmaf(h2, s, bv), 0.f) + fmaxf(fmaf(h3, s, bv), 0.f);
                pa += __shfl_xor_sync(0xffffffffu, pa, 1);
                pa += __shfl_xor_sync(0xffffffffu, pa, 2);
                if ((lane & 3) == 0)
                    dst[og * TP + g * 8 + ptq] = pa;
            }
        } else {
            #pragma unroll
            for (int g = 0; g < 2; g++) {
                float bv = (MODE == 0) ? pb0s[og * TP + g * 8 + ptq] : bias[og];
                float h0, h1, h2, h3;
                unpack2(acc[o][2*g],   h0, h1);
                unpack2(acc[o][2*g+1], h2, h3);
                h0 = fmaxf(fmaf(h0, s, bv), 0.f);
                h1 = fmaxf(fmaf(h1, s, bv), 0.f);
                h2 = fmaxf(fmaf(h2, s, bv), 0.f);
                h3 = fmaxf(fmaf(h3, s, bv), 0.f);
                *(float4*)(dst + og * RR + g * 128 + lane * 4)
                    = make_float4(h0, h1, h2, h3);
            }
        }
    }
}

// ---------------------------------------------------------------------------
// Main kernel, 128 threads, TP=16 points (256 rows), 2 CTAs/SM.
// Smem layout (float offsets), 27008 floats = 105.5 KB:
//   0     sW0hd u64[32o][32k]  (2048 f)
//   2048  sW1d  u64[32o][32k]  (2048 f)
//   4096  sW2d  u64[64o][32k]  (4096 f)
//   8192  ss0,sb0,ss1,sb1 (32 ea)     8320  ss2,sb2,ssc,sbc (64 ea)
//   8576  CF[32c][16]   9088 pb0s[32o][16]   9600 red[64o][16]
//   10624 XA[32][256]   18816 XB[32][256]
// ---------------------------------------------------------------------------
#define SMEM_FLOATS 27008

__global__ void __launch_bounds__(128, 2) main_kernel(
    const float* __restrict__ W0, const float* __restrict__ g0, const float* __restrict__ bb0,
    const float* __restrict__ W1, const float* __restrict__ g1, const float* __restrict__ bb1,
    const float* __restrict__ W2, const float* __restrict__ g2, const float* __restrict__ bb2,
    const float* __restrict__ SW, const float* __restrict__ sg, const float* __restrict__ sb,
    float* __restrict__ out)
{
    extern __shared__ float sm[];
    u64*   sW0hd = (u64*)(sm);          // [32][32] u64
    u64*   sW1d  = (u64*)(sm + 2048);   // [32][32] u64
    u64*   sW2d  = (u64*)(sm + 4096);   // [64][32] u64
    float* ss0   = sm + 8192;
    float* sb0   = sm + 8224;
    float* ss1   = sm + 8256;
    float* sb1   = sm + 8288;
    float* ss2   = sm + 8320;
    float* sb2   = sm + 8384;
    float* ssc   = sm + 8448;
    float* sbc   = sm + 8512;
    float* CF    = sm + 8576;
    float* pb0s  = sm + 9088;
    float* red   = sm + 9600;
    float* XA    = sm + 10624;
    float* XB    = sm + 18816;

    const int tid  = threadIdx.x;
    const int base = blockIdx.x * TP;
    const int b    = base >> 12;
    const int p0   = base & (NP - 1);

    // ---- stage duplicated u64 weights ([o][k]) + scales ----
    for (int i = tid; i < 1024; i += 128) {        // W0 high half
        int o = i >> 5, k = i & 31;
        float w = W0[o * 64 + 32 + k];
        sW0hd[i] = pack2(w, w);
    }
    for (int i = tid; i < 1024; i += 128) {        // W1 (o,k) row-major
        float w = W1[i];
        sW1d[i] = pack2(w, w);
    }
    for (int i = tid; i < 2048; i += 128) {        // W2 (o,k) row-major
        float w = W2[i];
        sW2d[i] = pack2(w, w);
    }
    if (tid < 32) { ss0[tid] = g0[tid] * INVC; sb0[tid] = bb0[tid];
                    ss1[tid] = g1[tid] * INVC; sb1[tid] = bb1[tid]; }
    else if (tid < 96) { int o = tid - 32;
                    ss2[o] = g2[o] * INVC; sb2[o] = bb2[o];
                    ssc[o] = sg[o] * INVC; sbc[o] = sb[o]; }

    const float* __restrict__ fT = g_featT + (size_t)b * NP * CH;

    // ---- stage CF[c][pt] ----
    {
        int pt = tid >> 3;
        int c0 = (tid & 7) * 4;
        float4 v = *(const float4*)(fT + (size_t)(p0 + pt) * CH + c0);
        CF[(c0+0) * TP + pt] = v.x;
        CF[(c0+1) * TP + pt] = v.y;
        CF[(c0+2) * TP + pt] = v.z;
        CF[(c0+3) * TP + pt] = v.w;
    }

    // ---- stage XH: thread handles rows 2*tid, 2*tid+1 (same pt) ----
    {
        int r0s = tid * 2;
        int pt  = r0s >> 4;
        int k0  = r0s & 15;
        const int* ipp = g_idx + (((size_t)b * NP + p0 + pt) << 4);
        int q0 = ipp[k0];
        int q1 = ipp[k0 + 1];
        const float4* qa = (const float4*)(fT + (size_t)q0 * CH);
        const float4* qb = (const float4*)(fT + (size_t)q1 * CH);
        const float4* pp = (const float4*)(fT + (size_t)(p0 + pt) * CH);
        #pragma unroll
        for (int i = 0; i < 8; i++) {
            float4 a0 = qa[i], a1 = qb[i], cv = pp[i];
            *(float2*)(XA + (4*i+0) * RR + r0s) = make_float2(a0.x - cv.x, a1.x - cv.x);
            *(float2*)(XA + (4*i+1) * RR + r0s) = make_float2(a0.y - cv.y, a1.y - cv.y);
            *(float2*)(XA + (4*i+2) * RR + r0s) = make_float2(a0.z - cv.z, a1.z - cv.z);
            *(float2*)(XA + (4*i+3) * RR + r0s) = make_float2(a0.w - cv.w, a1.w - cv.w);
        }
    }
    __syncthreads();

    // ---- pb0[o][pt]: W0 low half read from global (L2-resident, 4KB) ----
    {
        int pt  = tid & 15;
        int o0p = (tid >> 4) * 4;      // 8 groups x 4 o = 32 o
        float a[4] = {0.f, 0.f, 0.f, 0.f};
        #pragma unroll
        for (int j = 0; j < 4; j++) {
            const float* wr = W0 + (o0p + j) * 64;   // low half = first 32
            float acc = 0.f;
            #pragma unroll
            for (int c4 = 0; c4 < 8; c4++) {
                float4 w = *(const float4*)(wr + c4 * 4);
                acc = fmaf(w.x, CF[(c4*4+0) * TP + pt], acc);
                acc = fmaf(w.y, CF[(c4*4+1) * TP + pt], acc);
                acc = fmaf(w.z, CF[(c4*4+2) * TP + pt], acc);
                acc = fmaf(w.w, CF[(c4*4+3) * TP + pt], acc);
            }
            a[j] = acc;
        }
        #pragma unroll
        for (int j = 0; j < 4; j++) {
            int o = o0p + j;
            pb0s[o * TP + pt] = fmaf(a[j], ss0[o], sb0[o]);
        }
    }
    __syncthreads();

    const int w_   = tid >> 5;
    const int lane = tid & 31;

    gemm_stage<0>(XA, XB, sW0hd, w_ * 8, ss0, sb0, pb0s, lane);
    __syncthreads();
    gemm_stage<1>(XB, XA, sW1d,  w_ * 8, ss1, sb1, pb0s, lane);
    __syncthreads();
    gemm_stage<2>(XA, red, sW2d, w_ * 8,      ss2, sb2, pb0s, lane);
    gemm_stage<2>(XA, red, sW2d, 32 + w_ * 8, ss2, sb2, pb0s, lane);
    __syncthreads();

    // ---- shortcut + mean + final relu; SW read from global (L2, 8KB) ----
    {
        int pt  = tid & 15;
        int o0s = (tid >> 4) * 8;      // 8 groups x 8 o = 64 o
        float a[8];
        #pragma unroll
        for (int j = 0; j < 8; j++) a[j] = 0.f;
        #pragma unroll
        for (int j = 0; j < 8; j++) {
            const float* wr = SW + (o0s + j) * 32;
            float acc = 0.f;
            #pragma unroll
            for (int c4 = 0; c4 < 8; c4++) {
                float4 w = *(const float4*)(wr + c4 * 4);
                acc = fmaf(w.x, CF[(c4*4+0) * TP + pt], acc);
                acc = fmaf(w.y, CF[(c4*4+1) * TP + pt], acc);
                acc = fmaf(w.z, CF[(c4*4+2) * TP + pt], acc);
                acc = fmaf(w.w, CF[(c4*4+3) * TP + pt], acc);
            }
            a[j] = acc;
        }
        #pragma unroll
        for (int j = 0; j < 8; j++) {
            int o = o0s + j;
            float v = fmaf(a[j], ssc[o], sbc[o]) + red[o * TP + pt] * (1.0f / 16.0f);
            out[((size_t)b * 64 + o) * NP + p0 + pt] = fmaxf(v, 0.f);
        }
    }
}

// ---------------------------------------------------------------------------
extern "C" void kernel_launch(void* const* d_in, const int* in_sizes, int n_in,
                              void* d_out, int out_size)
{
    (void)in_sizes; (void)n_in; (void)out_size;
    const float* features = (const float*)d_in[1];
    const int*   ef       = (const int*)d_in[2];

    static bool attr_set = false;
    if (!attr_set) {
        cudaFuncSetAttribute(main_kernel,
                             cudaFuncAttributeMaxDynamicSharedMemorySize,
                             SMEM_FLOATS * (int)sizeof(float));
        attr_set = true;
    }

    prep_kernel<<<BATCH * 256, 256>>>(ef);
    {
        dim3 tg(EDG / 256, BATCH);
        scatter_kernel<<<tg, 256>>>(ef);
    }
    {
        dim3 tb(32, 8), tg(NP / 32, BATCH);
        transpose_kernel<<<tg, tb>>>(features);
    }
    main_kernel<<<(BATCH * NP) / TP, 128, SMEM_FLOATS * sizeof(float)>>>(
        (const float*)d_in[3],  (const float*)d_in[4],  (const float*)d_in[5],
        (const float*)d_in[6],  (const float*)d_in[7],  (const float*)d_in[8],
        (const float*)d_in[9],  (const float*)d_in[10], (const float*)d_in[11],
        (const float*)d_in[12], (const float*)d_in[13], (const float*)d_in[14],
        (float*)d_out);
}